// round 14
// baseline (speedup 1.0000x reference)
#include <cuda_runtime.h>
#include <cuda_bf16.h>
#include <cstdint>

// Problem constants (fixed by the dataset)
#define B_SZ   1024
#define NIN    2048
#define NOUT   2048
#define NC     10
#define TSTEPS 10

#define DECAY  0.2f
#define THRESH 0.5f
#define TD     0.1f   // THRESH * DECAY
#define RISK_DELTA 2.5e-4f

// Scratch
__device__ float g_h[B_SZ * NOUT];
__device__ float g_lossPartial[B_SZ];
__device__ int   g_riskList[B_SZ * NOUT];
__device__ int   g_riskCount;
// 2-way bf16 splits of x and W_enc (16B-aligned for cp.async)
__device__ __align__(16) __nv_bfloat16 g_Asp[2 * B_SZ * NIN];   // 8 MB
__device__ __align__(16) __nv_bfloat16 g_Bsp[2 * NOUT * NIN];   // 16 MB

// ---------------------------------------------------------------------------
// Packed fp32x2 helpers (for the snn kernel)
// ---------------------------------------------------------------------------
__device__ __forceinline__ unsigned long long pack2(float lo, float hi) {
    unsigned long long d;
    asm("mov.b64 %0, {%1, %2};" : "=l"(d)
        : "r"(__float_as_int(lo)), "r"(__float_as_int(hi)));
    return d;
}
__device__ __forceinline__ void unpack2(unsigned long long v, float& lo, float& hi) {
    int a, b;
    asm("mov.b64 {%0, %1}, %2;" : "=r"(a), "=r"(b) : "l"(v));
    lo = __int_as_float(a); hi = __int_as_float(b);
}
__device__ __forceinline__ unsigned long long ffma2(unsigned long long a,
                                                    unsigned long long b,
                                                    unsigned long long c) {
    unsigned long long d;
    asm("fma.rn.f32x2 %0, %1, %2, %3;" : "=l"(d) : "l"(a), "l"(b), "l"(c));
    return d;
}
__device__ __forceinline__ unsigned long long fadd2(unsigned long long a,
                                                    unsigned long long b) {
    unsigned long long d;
    asm("add.rn.f32x2 %0, %1, %2;" : "=l"(d) : "l"(a), "l"(b));
    return d;
}

// ---------------------------------------------------------------------------
// sm_80-era PTX helpers (valid on compute_103 base target)
// ---------------------------------------------------------------------------
__device__ __forceinline__ uint32_t smem_u32(const void* p) {
    uint32_t a;
    asm("{ .reg .u64 t; cvta.to.shared.u64 t, %1; cvt.u32.u64 %0, t; }"
        : "=r"(a) : "l"(p));
    return a;
}
__device__ __forceinline__ void cp16(uint32_t saddr, const void* gaddr) {
    asm volatile("cp.async.cg.shared.global [%0], [%1], 16;"
                 :: "r"(saddr), "l"(gaddr) : "memory");
}
__device__ __forceinline__ void cp_commit() {
    asm volatile("cp.async.commit_group;" ::: "memory");
}
__device__ __forceinline__ void ldm_x4(uint32_t* r, uint32_t addr) {
    asm volatile("ldmatrix.sync.aligned.m8n8.x4.shared.b16 {%0,%1,%2,%3}, [%4];"
                 : "=r"(r[0]), "=r"(r[1]), "=r"(r[2]), "=r"(r[3]) : "r"(addr));
}
__device__ __forceinline__ void mma16816(float* c, const uint32_t* a,
                                         uint32_t b0, uint32_t b1) {
    asm volatile(
        "mma.sync.aligned.m16n8k16.row.col.f32.bf16.bf16.f32 "
        "{%0,%1,%2,%3}, {%4,%5,%6,%7}, {%8,%9}, {%0,%1,%2,%3};"
        : "+f"(c[0]), "+f"(c[1]), "+f"(c[2]), "+f"(c[3])
        : "r"(a[0]), "r"(a[1]), "r"(a[2]), "r"(a[3]), "r"(b0), "r"(b1));
}

// ---------------------------------------------------------------------------
// Kernel Z: zero the risky counter (runs first; stream-ordered).
// ---------------------------------------------------------------------------
__global__ void zero_count(int* cnt) { *cnt = 0; }

// ---------------------------------------------------------------------------
// Kernel 0: 2-way bf16 split (exact residual).
// ---------------------------------------------------------------------------
struct __align__(8) bf4 { __nv_bfloat16 v[4]; };

__global__ void split2(const float* __restrict__ in, __nv_bfloat16* __restrict__ o0,
                       __nv_bfloat16* __restrict__ o1, int n4)
{
    int i = blockIdx.x * blockDim.x + threadIdx.x;
    if (i >= n4) return;
    float4 f = ((const float4*)in)[i];
    bf4 a0, a1;
#pragma unroll
    for (int e = 0; e < 4; e++) {
        float v = (&f.x)[e];
        __nv_bfloat16 b0 = __float2bfloat16_rn(v);
        float r = v - __bfloat162float(b0);
        a0.v[e] = b0;
        a1.v[e] = __float2bfloat16_rn(r);
    }
    ((bf4*)o0)[i] = a0;
    ((bf4*)o1)[i] = a1;
}

// ---------------------------------------------------------------------------
// Kernel 1: h ~= x @ W_enc^T via warp-level bf16 mma.sync, 3-pass 2-way split.
// CTA tile 128x128, 256 threads (8 warps, 2m x 4n grid, each warp 64x32).
// Passes (1,0),(0,1),(0,0), all chained in-MMA. Accuracy target ~1e-4
// (repair patches the rest).
// ---------------------------------------------------------------------------
#define NTILES  96       // 3 passes * 32 k64-tiles
#define SMEM_GEMM (4 * 16384)   // A0,B0,A1,B1

__global__ __launch_bounds__(256, 1)
void gemm_mma_bf16(float* __restrict__ C,
                   const __nv_bfloat16* __restrict__ A2,
                   const __nv_bfloat16* __restrict__ B2)
{
    extern __shared__ char sm[];
    const uint32_t sb = smem_u32(sm);
    const int tid = threadIdx.x;
    const int l = tid & 31;
    const int w = tid >> 5;
    const int warp_m = (w >> 2) * 64;    // {0, 64}
    const int warp_n = (w & 3) * 32;     // {0, 32, 64, 96}
    const int bm = blockIdx.y * 128;
    const int bn = blockIdx.x * 128;

    // pass -> (A split idx, B split idx): (1,0),(0,1),(0,0)
    const uint32_t AI_PK = 0x001u;
    const uint32_t BI_PK = 0x010u;

    float c[4][4][4];   // [mi(m16)][ni(n8)][frag]
#pragma unroll
    for (int mi = 0; mi < 4; mi++)
#pragma unroll
        for (int ni = 0; ni < 4; ni++)
#pragma unroll
            for (int q = 0; q < 4; q++) c[mi][ni][q] = 0.0f;

    // Per-lane ldmatrix row/chunk components (constant across tiles).
    const int arow = warp_m + (l & 15);                    // + 16*mi
    const int achb = (l >> 4);                             // + 2*kb
    const int brow = warp_n + (l & 7) + ((l >> 4) << 3);   // + 16*bi
    const int bchb = ((l >> 3) & 1);                       // + 2*kb

    auto load_tile = [&](int tl, int buf) {
        const int pass = tl >> 5;
        const int kt = tl & 31;
        const int ai = (AI_PK >> (4 * pass)) & 0xF;
        const int bi = (BI_PK >> (4 * pass)) & 0xF;
        const __nv_bfloat16* gA = A2 + (size_t)ai * (B_SZ * NIN)
                                     + (size_t)bm * NIN + kt * 64;
        const __nv_bfloat16* gB = B2 + (size_t)bi * (NOUT * NIN)
                                     + (size_t)bn * NIN + kt * 64;
        const uint32_t ab = sb + buf * 32768;
        const uint32_t bb = ab + 16384;
#pragma unroll
        for (int j = 0; j < 4; j++) {
            const int cid = j * 256 + tid;        // 0..1023
            const int row = cid >> 3, ch = cid & 7;
            const uint32_t sw = (uint32_t)row * 128 + (uint32_t)(ch ^ (row & 7)) * 16;
            cp16(ab + sw, gA + (size_t)row * NIN + ch * 8);
            cp16(bb + sw, gB + (size_t)row * NIN + ch * 8);
        }
        cp_commit();
    };

    auto ld_frags = [&](uint32_t ab, uint32_t bb, int kb,
                        uint32_t fa[4][4], uint32_t fb[2][4]) {
#pragma unroll
        for (int mi = 0; mi < 4; mi++) {
            const int row = arow + 16 * mi;
            const int ch = 2 * kb + achb;
            ldm_x4(fa[mi], ab + row * 128 + ((ch ^ (row & 7)) * 16));
        }
#pragma unroll
        for (int bi = 0; bi < 2; bi++) {
            const int row = brow + 16 * bi;
            const int ch = 2 * kb + bchb;
            ldm_x4(fb[bi], bb + row * 128 + ((ch ^ (row & 7)) * 16));
        }
    };

    uint32_t FA[2][4][4], FB[2][2][4];

    load_tile(0, 0);
    for (int tl = 0; tl < NTILES; tl++) {
        const int buf = tl & 1;
        if (tl + 1 < NTILES) {
            load_tile(tl + 1, buf ^ 1);
            asm volatile("cp.async.wait_group 1;" ::: "memory");
        } else {
            asm volatile("cp.async.wait_group 0;" ::: "memory");
        }
        __syncthreads();

        const uint32_t ab = sb + buf * 32768;
        const uint32_t bb = ab + 16384;

        ld_frags(ab, bb, 0, FA[0], FB[0]);
#pragma unroll
        for (int kb = 0; kb < 4; kb++) {
            if (kb < 3) ld_frags(ab, bb, kb + 1, FA[(kb + 1) & 1], FB[(kb + 1) & 1]);
            uint32_t (*fa)[4] = FA[kb & 1];
            uint32_t (*fb)[4] = FB[kb & 1];
#pragma unroll
            for (int mi = 0; mi < 4; mi++)
#pragma unroll
                for (int bi = 0; bi < 2; bi++) {
                    mma16816(c[mi][2 * bi],     fa[mi], fb[bi][0], fb[bi][1]);
                    mma16816(c[mi][2 * bi + 1], fa[mi], fb[bi][2], fb[bi][3]);
                }
        }
        __syncthreads();
    }

    // Epilogue: fragment layout -> global fp32.
#pragma unroll
    for (int mi = 0; mi < 4; mi++)
#pragma unroll
        for (int ni = 0; ni < 4; ni++) {
            const int row = bm + warp_m + 16 * mi + (l >> 2);
            const int col = bn + warp_n + 8 * ni + (l & 3) * 2;
            float2 v0; v0.x = c[mi][ni][0]; v0.y = c[mi][ni][1];
            float2 v1; v1.x = c[mi][ni][2]; v1.y = c[mi][ni][3];
            *(float2*)&C[(size_t)row * NOUT + col]       = v0;
            *(float2*)&C[(size_t)(row + 8) * NOUT + col] = v1;
        }
}

// ---------------------------------------------------------------------------
// Kernel 1b-A: detect threshold-risky neurons, append to compact list
// (warp-aggregated atomics: 1 atomicAdd per warp).
// ---------------------------------------------------------------------------
__global__ __launch_bounds__(256)
void detect_risky(const float* __restrict__ h, int* __restrict__ list,
                  int* __restrict__ count)
{
    const int idx = blockIdx.x * blockDim.x + threadIdx.x;
    const int lane = threadIdx.x & 31;

    const float hv = h[idx];
    float mem = 0.0f, spk = 0.0f;
    bool risky = false;
#pragma unroll
    for (int t = 0; t < TSTEPS; t++) {
        mem = mem * DECAY + hv - spk * TD;
        const float d = mem - THRESH;
        risky |= (fabsf(d) < RISK_DELTA);
        spk = (d > 0.0f) ? 1.0f : 0.0f;
    }

    const unsigned mask = __ballot_sync(0xffffffffu, risky);
    if (mask == 0) return;
    const int leader = __ffs(mask) - 1;
    int base = 0;
    if (lane == leader) base = atomicAdd(count, __popc(mask));
    base = __shfl_sync(0xffffffffu, base, leader);
    if (risky)
        list[base + __popc(mask & ((1u << lane) - 1u))] = idx;
}

// ---------------------------------------------------------------------------
// Kernel 1b-B: repair risky neurons. Grid-strided over the compacted list;
// every lane handles a different neuron. Arithmetic identical to R12/R13
// repair (k-ascending fp32 fmaf, single accumulator) -> identical values.
// ---------------------------------------------------------------------------
__global__ __launch_bounds__(256)
void repair_risky(float* __restrict__ h, const float* __restrict__ x,
                  const float* __restrict__ W, const int* __restrict__ list,
                  const int* __restrict__ count)
{
    const int n = *count;
    for (int i = blockIdx.x * blockDim.x + threadIdx.x; i < n;
         i += gridDim.x * blockDim.x) {
        const int idx = list[i];
        const int b = idx >> 11;            // / NOUT
        const int j = idx & (NOUT - 1);
        const float* xr = x + (size_t)b * NIN;
        const float* wr = W + (size_t)j * NIN;
        float acc = 0.0f;
        for (int k = 0; k < NIN; k += 4) {
            const float4 xv = *(const float4*)(xr + k);
            const float4 wv = *(const float4*)(wr + k);
            acc = fmaf(xv.x, wv.x, acc);
            acc = fmaf(xv.y, wv.y, acc);
            acc = fmaf(xv.z, wv.z, acc);
            acc = fmaf(xv.w, wv.w, acc);
        }
        h[idx] = acc;
    }
}

// ---------------------------------------------------------------------------
// Kernel 2: SNN recurrence (R5 version — measured best). One CTA per row.
// ---------------------------------------------------------------------------
__global__ __launch_bounds__(256)
void snn_steps(const float* __restrict__ h, const float* __restrict__ Wdec,
               const float* __restrict__ yoh, float* __restrict__ out,
               float* __restrict__ lossPartial)
{
    __shared__ float red[8 * NC + NC];

    const int b = blockIdx.x;
    const int tid = threadIdx.x;
    const int warp = tid >> 5, lane = tid & 31;

    unsigned long long w2[8][5];
#pragma unroll
    for (int i = 0; i < 8; i++) {
        const int j = tid + 256 * i;
#pragma unroll
        for (int cc = 0; cc < 5; cc++)
            w2[i][cc] = pack2(Wdec[(2 * cc) * NOUT + j],
                              Wdec[(2 * cc + 1) * NOUT + j]);
    }

    float hreg[8], mem[8], spk[8];
#pragma unroll
    for (int i = 0; i < 8; i++) {
        hreg[i] = h[(size_t)b * NOUT + tid + 256 * i];
        mem[i] = 0.0f; spk[i] = 0.0f;
    }

    float ym = 0.0f, ys = 0.0f, yo = 0.0f, lossc = 0.0f;
    if (tid < NC) yo = yoh[b * NC + tid];
    __syncthreads();

    for (int t = 0; t < TSTEPS; t++) {
        unsigned long long acc2[5];
#pragma unroll
        for (int cc = 0; cc < 5; cc++) acc2[cc] = 0ull;

#pragma unroll
        for (int i = 0; i < 8; i++) {
            mem[i] = mem[i] * DECAY + hreg[i] - spk[i] * TD;
            spk[i] = (mem[i] > THRESH) ? 1.0f : 0.0f;
            const int j = tid + 256 * i;
            out[(size_t)t * (B_SZ * NOUT) + (size_t)b * NOUT + j] = spk[i];
            const unsigned long long s2 = pack2(spk[i], spk[i]);
#pragma unroll
            for (int cc = 0; cc < 5; cc++)
                acc2[cc] = ffma2(s2, w2[i][cc], acc2[cc]);
        }

#pragma unroll
        for (int cc = 0; cc < 5; cc++) {
#pragma unroll
            for (int o = 16; o > 0; o >>= 1) {
                unsigned long long other =
                    __shfl_down_sync(0xffffffffu, acc2[cc], o);
                acc2[cc] = fadd2(acc2[cc], other);
            }
        }
        if (lane == 0) {
#pragma unroll
            for (int cc = 0; cc < 5; cc++) {
                float lo, hi;
                unpack2(acc2[cc], lo, hi);
                red[warp * NC + 2 * cc]     = lo;
                red[warp * NC + 2 * cc + 1] = hi;
            }
        }
        __syncthreads();

        if (tid < NC) {
            float tot = 0.0f;
#pragma unroll
            for (int ww = 0; ww < 8; ww++) tot += red[ww * NC + tid];
            ym = ym * DECAY + tot - ys * TD;
            ys = (ym > THRESH) ? 1.0f : 0.0f;
            const float d = ys - yo;
            lossc = fmaf(d, d, lossc);
        }
        __syncthreads();
    }

    if (tid < NC) red[8 * NC + tid] = lossc;
    __syncthreads();
    if (tid == 0) {
        float s = 0.0f;
#pragma unroll
        for (int cc = 0; cc < NC; cc++) s += red[8 * NC + cc];
        lossPartial[b] = s;
    }
}

// ---------------------------------------------------------------------------
// Kernel 3: reduce per-row loss partials -> out[out_size-1]
// ---------------------------------------------------------------------------
__global__ void loss_reduce(const float* __restrict__ lp, float* __restrict__ out,
                            int out_size)
{
    __shared__ float s[256];
    float v = 0.0f;
    for (int i = threadIdx.x; i < B_SZ; i += 256) v += lp[i];
    s[threadIdx.x] = v;
    __syncthreads();
    for (int o = 128; o > 0; o >>= 1) {
        if (threadIdx.x < o) s[threadIdx.x] += s[threadIdx.x + o];
        __syncthreads();
    }
    if (threadIdx.x == 0)
        out[out_size - 1] = s[0] / (float)(B_SZ * NC);
}

// ---------------------------------------------------------------------------
extern "C" void kernel_launch(void* const* d_in, const int* in_sizes, int n_in,
                              void* d_out, int out_size)
{
    const float* x     = (const float*)d_in[0];   // [1024, 2048]
    const float* W_enc = (const float*)d_in[1];   // [2048, 2048]
    const float* W_dec = (const float*)d_in[2];   // [10, 2048]
    const float* y_oh  = (const float*)d_in[3];   // [1024, 10]
    float* out = (float*)d_out;

    float *h, *lp;
    cudaGetSymbolAddress((void**)&h, g_h);
    cudaGetSymbolAddress((void**)&lp, g_lossPartial);
    __nv_bfloat16 *a2, *b2;
    cudaGetSymbolAddress((void**)&a2, g_Asp);
    cudaGetSymbolAddress((void**)&b2, g_Bsp);
    int *rl, *rc;
    cudaGetSymbolAddress((void**)&rl, g_riskList);
    cudaGetSymbolAddress((void**)&rc, g_riskCount);

    // Zero the risky counter (stream-ordered before detect).
    zero_count<<<1, 1>>>(rc);

    // Split x and W_enc into 2 bf16 components each.
    const int nA = B_SZ * NIN, nB = NOUT * NIN;
    split2<<<(nA / 4 + 255) / 256, 256>>>(x, a2, a2 + nA, nA / 4);
    split2<<<(nB / 4 + 255) / 256, 256>>>(W_enc, b2, b2 + nB, nB / 4);

    // Approximate tensor-core GEMM (grid 16 x 8 = 128 CTAs, 8 warps each).
    cudaFuncSetAttribute(gemm_mma_bf16, cudaFuncAttributeMaxDynamicSharedMemorySize,
                         SMEM_GEMM);
    gemm_mma_bf16<<<dim3(NOUT / 128, B_SZ / 128), 256, SMEM_GEMM>>>(h, a2, b2);

    // Detect threshold-risky neurons (compact list), then repair exactly.
    detect_risky<<<(B_SZ * NOUT) / 256, 256>>>(h, rl, rc);
    repair_risky<<<296, 256>>>(h, x, W_enc, rl, rc);

    // Recurrence + loss
    snn_steps<<<B_SZ, 256>>>(h, W_dec, y_oh, out, lp);
    loss_reduce<<<1, 256>>>(lp, out, out_size);
}

// round 15
// speedup vs baseline: 1.4455x; 1.4455x over previous
#include <cuda_runtime.h>
#include <cuda_bf16.h>
#include <cstdint>

// Problem constants (fixed by the dataset)
#define B_SZ   1024
#define NIN    2048
#define NOUT   2048
#define NC     10
#define TSTEPS 10

#define DECAY  0.2f
#define THRESH 0.5f
#define TD     0.1f   // THRESH * DECAY
#define RISK_DELTA 2.5e-4f

// Scratch
__device__ float g_h[B_SZ * NOUT];
__device__ float g_lossPartial[B_SZ];
__device__ int   g_riskList[B_SZ * NOUT];
__device__ int   g_riskCount;
// 2-way bf16 splits of x and W_enc (16B-aligned for cp.async)
__device__ __align__(16) __nv_bfloat16 g_Asp[2 * B_SZ * NIN];   // 8 MB
__device__ __align__(16) __nv_bfloat16 g_Bsp[2 * NOUT * NIN];   // 16 MB

// ---------------------------------------------------------------------------
// Packed fp32x2 helpers (for the snn kernel)
// ---------------------------------------------------------------------------
__device__ __forceinline__ unsigned long long pack2(float lo, float hi) {
    unsigned long long d;
    asm("mov.b64 %0, {%1, %2};" : "=l"(d)
        : "r"(__float_as_int(lo)), "r"(__float_as_int(hi)));
    return d;
}
__device__ __forceinline__ void unpack2(unsigned long long v, float& lo, float& hi) {
    int a, b;
    asm("mov.b64 {%0, %1}, %2;" : "=r"(a), "=r"(b) : "l"(v));
    lo = __int_as_float(a); hi = __int_as_float(b);
}
__device__ __forceinline__ unsigned long long ffma2(unsigned long long a,
                                                    unsigned long long b,
                                                    unsigned long long c) {
    unsigned long long d;
    asm("fma.rn.f32x2 %0, %1, %2, %3;" : "=l"(d) : "l"(a), "l"(b), "l"(c));
    return d;
}
__device__ __forceinline__ unsigned long long fadd2(unsigned long long a,
                                                    unsigned long long b) {
    unsigned long long d;
    asm("add.rn.f32x2 %0, %1, %2;" : "=l"(d) : "l"(a), "l"(b));
    return d;
}

// ---------------------------------------------------------------------------
// sm_80-era PTX helpers (valid on compute_103 base target)
// ---------------------------------------------------------------------------
__device__ __forceinline__ uint32_t smem_u32(const void* p) {
    uint32_t a;
    asm("{ .reg .u64 t; cvta.to.shared.u64 t, %1; cvt.u32.u64 %0, t; }"
        : "=r"(a) : "l"(p));
    return a;
}
__device__ __forceinline__ void cp16(uint32_t saddr, const void* gaddr) {
    asm volatile("cp.async.cg.shared.global [%0], [%1], 16;"
                 :: "r"(saddr), "l"(gaddr) : "memory");
}
__device__ __forceinline__ void cp_commit() {
    asm volatile("cp.async.commit_group;" ::: "memory");
}
__device__ __forceinline__ void ldm_x4(uint32_t* r, uint32_t addr) {
    asm volatile("ldmatrix.sync.aligned.m8n8.x4.shared.b16 {%0,%1,%2,%3}, [%4];"
                 : "=r"(r[0]), "=r"(r[1]), "=r"(r[2]), "=r"(r[3]) : "r"(addr));
}
__device__ __forceinline__ void mma16816(float* c, const uint32_t* a,
                                         uint32_t b0, uint32_t b1) {
    asm volatile(
        "mma.sync.aligned.m16n8k16.row.col.f32.bf16.bf16.f32 "
        "{%0,%1,%2,%3}, {%4,%5,%6,%7}, {%8,%9}, {%0,%1,%2,%3};"
        : "+f"(c[0]), "+f"(c[1]), "+f"(c[2]), "+f"(c[3])
        : "r"(a[0]), "r"(a[1]), "r"(a[2]), "r"(a[3]), "r"(b0), "r"(b1));
}

// ---------------------------------------------------------------------------
// Kernel 0: 2-way bf16 split (exact residual). Variant A also zeroes the
// risky counter (block 0 thread 0) — ordered before the GEMM appends.
// ---------------------------------------------------------------------------
struct __align__(8) bf4 { __nv_bfloat16 v[4]; };

__global__ void split2(const float* __restrict__ in, __nv_bfloat16* __restrict__ o0,
                       __nv_bfloat16* __restrict__ o1, int n4, int* cnt)
{
    int i = blockIdx.x * blockDim.x + threadIdx.x;
    if (cnt && i == 0) *cnt = 0;
    if (i >= n4) return;
    float4 f = ((const float4*)in)[i];
    bf4 a0, a1;
#pragma unroll
    for (int e = 0; e < 4; e++) {
        float v = (&f.x)[e];
        __nv_bfloat16 b0 = __float2bfloat16_rn(v);
        float r = v - __bfloat162float(b0);
        a0.v[e] = b0;
        a1.v[e] = __float2bfloat16_rn(r);
    }
    ((bf4*)o0)[i] = a0;
    ((bf4*)o1)[i] = a1;
}

// ---------------------------------------------------------------------------
// Kernel 1: h ~= x @ W_enc^T, pass-fused: per K-tile load A0,A1,B0,B1 once
// and chain (a1b0 + a0b1 + a0b0) into the accumulator. CTA 128x128, 256 thr
// (8 warps, 2m x 4n, warp tile 64x32). Epilogue writes h AND detects
// threshold-risky neurons (10-step sim on in-register h), appending to the
// compact risk list via warp-aggregated atomics.
// ---------------------------------------------------------------------------
#define NKT 32                      // k64-tiles
#define TILE_B 16384
#define BUF_B (4 * TILE_B)          // A0,A1,B0,B1
#define SMEM_GEMM (2 * BUF_B)       // double-buffered: 128 KB

__global__ __launch_bounds__(256, 1)
void gemm_mma_bf16(float* __restrict__ C,
                   const __nv_bfloat16* __restrict__ A2,
                   const __nv_bfloat16* __restrict__ B2,
                   int* __restrict__ list, int* __restrict__ count)
{
    extern __shared__ char sm[];
    const uint32_t sb = smem_u32(sm);
    const int tid = threadIdx.x;
    const int l = tid & 31;
    const int w = tid >> 5;
    const int warp_m = (w >> 2) * 64;    // {0, 64}
    const int warp_n = (w & 3) * 32;     // {0, 32, 64, 96}
    const int bm = blockIdx.y * 128;
    const int bn = blockIdx.x * 128;

    float c[4][4][4];   // [mi(m16)][ni(n8)][frag]
#pragma unroll
    for (int mi = 0; mi < 4; mi++)
#pragma unroll
        for (int ni = 0; ni < 4; ni++)
#pragma unroll
            for (int q = 0; q < 4; q++) c[mi][ni][q] = 0.0f;

    // Per-lane ldmatrix row/chunk components (constant across tiles).
    const int arow = warp_m + (l & 15);                    // + 16*mi
    const int achb = (l >> 4);                             // + 2*kb
    const int brow = warp_n + (l & 7) + ((l >> 4) << 3);   // + 16*bi
    const int bchb = ((l >> 3) & 1);                       // + 2*kb

    // Tile source pointers: [A0, A1, B0, B1]
    const __nv_bfloat16* srcs[4];
    srcs[0] = A2 + (size_t)bm * NIN;
    srcs[1] = A2 + (size_t)(B_SZ * NIN) + (size_t)bm * NIN;
    srcs[2] = B2 + (size_t)bn * NIN;
    srcs[3] = B2 + (size_t)(NOUT * NIN) + (size_t)bn * NIN;

    auto load_tile = [&](int kt, int buf) {
        const uint32_t base = sb + buf * BUF_B;
#pragma unroll
        for (int j = 0; j < 16; j++) {
            const int cid = j * 256 + tid;        // 0..4095
            const int tile = cid >> 10;           // 0..3
            const int e = cid & 1023;
            const int row = e >> 3, ch = e & 7;
            const uint32_t sw = (uint32_t)row * 128 + (uint32_t)(ch ^ (row & 7)) * 16;
            cp16(base + tile * TILE_B + sw,
                 srcs[tile] + (size_t)row * NIN + kt * 64 + ch * 8);
        }
        cp_commit();
    };

    load_tile(0, 0);
    for (int kt = 0; kt < NKT; kt++) {
        const int buf = kt & 1;
        if (kt + 1 < NKT) {
            load_tile(kt + 1, buf ^ 1);
            asm volatile("cp.async.wait_group 1;" ::: "memory");
        } else {
            asm volatile("cp.async.wait_group 0;" ::: "memory");
        }
        __syncthreads();

        const uint32_t a0b = sb + buf * BUF_B;
        const uint32_t a1b = a0b + TILE_B;
        const uint32_t b0b = a0b + 2 * TILE_B;
        const uint32_t b1b = a0b + 3 * TILE_B;

#pragma unroll
        for (int kb = 0; kb < 4; kb++) {
            uint32_t fa0[4][4], fa1[4][4], fb0[2][4], fb1[2][4];
#pragma unroll
            for (int mi = 0; mi < 4; mi++) {
                const int row = arow + 16 * mi;
                const int ch = 2 * kb + achb;
                const uint32_t off = row * 128 + ((ch ^ (row & 7)) * 16);
                ldm_x4(fa0[mi], a0b + off);
                ldm_x4(fa1[mi], a1b + off);
            }
#pragma unroll
            for (int bi = 0; bi < 2; bi++) {
                const int row = brow + 16 * bi;
                const int ch = 2 * kb + bchb;
                const uint32_t off = row * 128 + ((ch ^ (row & 7)) * 16);
                ldm_x4(fb0[bi], b0b + off);
                ldm_x4(fb1[bi], b1b + off);
            }
            // Residual products first, then dominant — all chained.
#pragma unroll
            for (int mi = 0; mi < 4; mi++)
#pragma unroll
                for (int bi = 0; bi < 2; bi++) {
                    mma16816(c[mi][2 * bi],     fa1[mi], fb0[bi][0], fb0[bi][1]);
                    mma16816(c[mi][2 * bi + 1], fa1[mi], fb0[bi][2], fb0[bi][3]);
                    mma16816(c[mi][2 * bi],     fa0[mi], fb1[bi][0], fb1[bi][1]);
                    mma16816(c[mi][2 * bi + 1], fa0[mi], fb1[bi][2], fb1[bi][3]);
                    mma16816(c[mi][2 * bi],     fa0[mi], fb0[bi][0], fb0[bi][1]);
                    mma16816(c[mi][2 * bi + 1], fa0[mi], fb0[bi][2], fb0[bi][3]);
                }
        }
        __syncthreads();
    }

    // Epilogue: write h, then detect risky neurons from registers.
#pragma unroll
    for (int mi = 0; mi < 4; mi++)
#pragma unroll
        for (int ni = 0; ni < 4; ni++) {
            const int row = bm + warp_m + 16 * mi + (l >> 2);
            const int col = bn + warp_n + 8 * ni + (l & 3) * 2;
            float2 v0; v0.x = c[mi][ni][0]; v0.y = c[mi][ni][1];
            float2 v1; v1.x = c[mi][ni][2]; v1.y = c[mi][ni][3];
            *(float2*)&C[(size_t)row * NOUT + col]       = v0;
            *(float2*)&C[(size_t)(row + 8) * NOUT + col] = v1;
        }

#pragma unroll
    for (int mi = 0; mi < 4; mi++)
#pragma unroll
        for (int ni = 0; ni < 4; ni++) {
            const int row0 = bm + warp_m + 16 * mi + (l >> 2);
            const int col0 = bn + warp_n + 8 * ni + (l & 3) * 2;
#pragma unroll
            for (int q = 0; q < 4; q++) {
                const float hv = c[mi][ni][q];
                const int row = row0 + ((q >> 1) << 3);
                const int col = col0 + (q & 1);
                float mem = 0.0f, spk = 0.0f;
                bool risky = false;
#pragma unroll
                for (int t = 0; t < TSTEPS; t++) {
                    mem = mem * DECAY + hv - spk * TD;
                    const float d = mem - THRESH;
                    risky |= (fabsf(d) < RISK_DELTA);
                    spk = (d > 0.0f) ? 1.0f : 0.0f;
                }
                const unsigned mask = __ballot_sync(0xffffffffu, risky);
                if (mask) {
                    const int leader = __ffs(mask) - 1;
                    int base = 0;
                    if (l == leader) base = atomicAdd(count, __popc(mask));
                    base = __shfl_sync(0xffffffffu, base, leader);
                    if (risky)
                        list[base + __popc(mask & ((1u << l) - 1u))]
                            = row * NOUT + col;
                }
            }
        }
}

// ---------------------------------------------------------------------------
// Kernel 1b: repair risky neurons. Worker id = tid*gridDim+blockIdx so that
// consecutive list entries land on DIFFERENT CTAs/SMs (the R13/R14 layout
// put all work in the first ~14 CTAs -> few SMs -> 130us). Arithmetic is
// byte-identical to R12-14 (k-ascending fp32 fmaf, single accumulator).
// ---------------------------------------------------------------------------
__global__ __launch_bounds__(32)
void repair_risky(float* __restrict__ h, const float* __restrict__ x,
                  const float* __restrict__ W, const int* __restrict__ list,
                  const int* __restrict__ count)
{
    const int n = *count;
    const int stride = gridDim.x * blockDim.x;
    for (int i = threadIdx.x * gridDim.x + blockIdx.x; i < n; i += stride) {
        const int idx = list[i];
        const int b = idx >> 11;            // / NOUT
        const int j = idx & (NOUT - 1);
        const float* xr = x + (size_t)b * NIN;
        const float* wr = W + (size_t)j * NIN;
        float acc = 0.0f;
        for (int k = 0; k < NIN; k += 4) {
            const float4 xv = *(const float4*)(xr + k);
            const float4 wv = *(const float4*)(wr + k);
            acc = fmaf(xv.x, wv.x, acc);
            acc = fmaf(xv.y, wv.y, acc);
            acc = fmaf(xv.z, wv.z, acc);
            acc = fmaf(xv.w, wv.w, acc);
        }
        h[idx] = acc;
    }
}

// ---------------------------------------------------------------------------
// Kernel 2: SNN recurrence (R5 version — measured best). One CTA per row.
// ---------------------------------------------------------------------------
__global__ __launch_bounds__(256)
void snn_steps(const float* __restrict__ h, const float* __restrict__ Wdec,
               const float* __restrict__ yoh, float* __restrict__ out,
               float* __restrict__ lossPartial)
{
    __shared__ float red[8 * NC + NC];

    const int b = blockIdx.x;
    const int tid = threadIdx.x;
    const int warp = tid >> 5, lane = tid & 31;

    unsigned long long w2[8][5];
#pragma unroll
    for (int i = 0; i < 8; i++) {
        const int j = tid + 256 * i;
#pragma unroll
        for (int cc = 0; cc < 5; cc++)
            w2[i][cc] = pack2(Wdec[(2 * cc) * NOUT + j],
                              Wdec[(2 * cc + 1) * NOUT + j]);
    }

    float hreg[8], mem[8], spk[8];
#pragma unroll
    for (int i = 0; i < 8; i++) {
        hreg[i] = h[(size_t)b * NOUT + tid + 256 * i];
        mem[i] = 0.0f; spk[i] = 0.0f;
    }

    float ym = 0.0f, ys = 0.0f, yo = 0.0f, lossc = 0.0f;
    if (tid < NC) yo = yoh[b * NC + tid];
    __syncthreads();

    for (int t = 0; t < TSTEPS; t++) {
        unsigned long long acc2[5];
#pragma unroll
        for (int cc = 0; cc < 5; cc++) acc2[cc] = 0ull;

#pragma unroll
        for (int i = 0; i < 8; i++) {
            mem[i] = mem[i] * DECAY + hreg[i] - spk[i] * TD;
            spk[i] = (mem[i] > THRESH) ? 1.0f : 0.0f;
            const int j = tid + 256 * i;
            out[(size_t)t * (B_SZ * NOUT) + (size_t)b * NOUT + j] = spk[i];
            const unsigned long long s2 = pack2(spk[i], spk[i]);
#pragma unroll
            for (int cc = 0; cc < 5; cc++)
                acc2[cc] = ffma2(s2, w2[i][cc], acc2[cc]);
        }

#pragma unroll
        for (int cc = 0; cc < 5; cc++) {
#pragma unroll
            for (int o = 16; o > 0; o >>= 1) {
                unsigned long long other =
                    __shfl_down_sync(0xffffffffu, acc2[cc], o);
                acc2[cc] = fadd2(acc2[cc], other);
            }
        }
        if (lane == 0) {
#pragma unroll
            for (int cc = 0; cc < 5; cc++) {
                float lo, hi;
                unpack2(acc2[cc], lo, hi);
                red[warp * NC + 2 * cc]     = lo;
                red[warp * NC + 2 * cc + 1] = hi;
            }
        }
        __syncthreads();

        if (tid < NC) {
            float tot = 0.0f;
#pragma unroll
            for (int ww = 0; ww < 8; ww++) tot += red[ww * NC + tid];
            ym = ym * DECAY + tot - ys * TD;
            ys = (ym > THRESH) ? 1.0f : 0.0f;
            const float d = ys - yo;
            lossc = fmaf(d, d, lossc);
        }
        __syncthreads();
    }

    if (tid < NC) red[8 * NC + tid] = lossc;
    __syncthreads();
    if (tid == 0) {
        float s = 0.0f;
#pragma unroll
        for (int cc = 0; cc < NC; cc++) s += red[8 * NC + cc];
        lossPartial[b] = s;
    }
}

// ---------------------------------------------------------------------------
// Kernel 3: reduce per-row loss partials -> out[out_size-1]
// ---------------------------------------------------------------------------
__global__ void loss_reduce(const float* __restrict__ lp, float* __restrict__ out,
                            int out_size)
{
    __shared__ float s[256];
    float v = 0.0f;
    for (int i = threadIdx.x; i < B_SZ; i += 256) v += lp[i];
    s[threadIdx.x] = v;
    __syncthreads();
    for (int o = 128; o > 0; o >>= 1) {
        if (threadIdx.x < o) s[threadIdx.x] += s[threadIdx.x + o];
        __syncthreads();
    }
    if (threadIdx.x == 0)
        out[out_size - 1] = s[0] / (float)(B_SZ * NC);
}

// ---------------------------------------------------------------------------
extern "C" void kernel_launch(void* const* d_in, const int* in_sizes, int n_in,
                              void* d_out, int out_size)
{
    const float* x     = (const float*)d_in[0];   // [1024, 2048]
    const float* W_enc = (const float*)d_in[1];   // [2048, 2048]
    const float* W_dec = (const float*)d_in[2];   // [10, 2048]
    const float* y_oh  = (const float*)d_in[3];   // [1024, 10]
    float* out = (float*)d_out;

    float *h, *lp;
    cudaGetSymbolAddress((void**)&h, g_h);
    cudaGetSymbolAddress((void**)&lp, g_lossPartial);
    __nv_bfloat16 *a2, *b2;
    cudaGetSymbolAddress((void**)&a2, g_Asp);
    cudaGetSymbolAddress((void**)&b2, g_Bsp);
    int *rl, *rc;
    cudaGetSymbolAddress((void**)&rl, g_riskList);
    cudaGetSymbolAddress((void**)&rc, g_riskCount);

    // Split x (also zeroes the risky counter) and W_enc.
    const int nA = B_SZ * NIN, nB = NOUT * NIN;
    split2<<<(nA / 4 + 255) / 256, 256>>>(x, a2, a2 + nA, nA / 4, rc);
    split2<<<(nB / 4 + 255) / 256, 256>>>(W_enc, b2, b2 + nB, nB / 4, nullptr);

    // Pass-fused tensor-core GEMM + in-register risk detection.
    cudaFuncSetAttribute(gemm_mma_bf16, cudaFuncAttributeMaxDynamicSharedMemorySize,
                         SMEM_GEMM);
    gemm_mma_bf16<<<dim3(NOUT / 128, B_SZ / 128), 256, SMEM_GEMM>>>(h, a2, b2,
                                                                    rl, rc);

    // Exact repair, spread across SMs (CTA-fastest worker mapping).
    repair_risky<<<4096, 32>>>(h, x, W_enc, rl, rc);

    // Recurrence + loss
    snn_steps<<<B_SZ, 256>>>(h, W_dec, y_oh, out, lp);
    loss_reduce<<<1, 256>>>(lp, out, out_size);
}